// round 15
// baseline (speedup 1.0000x reference)
#include <cuda_runtime.h>
#include <cstdint>

#define NN 100000
#define EE 1600000
#define HF 128
#define GG 128
#define LL 4
#define EPS_BN 1e-5f
#define BM 128
#define BK 32
#define ASTRIDE 132
#define SCAN_B 512
#define NB ((NN + SCAN_B - 1) / SCAN_B)   // 196
#define NTILE ((NN + BM - 1) / BM)        // 782

#define A_TILE (BK * ASTRIDE)             // 4224 floats
#define B_TILE (BK * HF)                  // 4096 floats
#define SMEMB ((2 * A_TILE + 2 * B_TILE) * 4)   // 66560 bytes

// ---------------- scratch (static device globals; no allocs allowed) ----------
__device__ float g_h[(size_t)NN * HF];       // buffer A (emb / raw rst ping-pong)
__device__ float g_rst[(size_t)NN * HF];     // buffer B
__device__ float g_agg[(size_t)NN * HF];     // BN-folded neighbor means
__device__ float g_rdeg[NN];
__device__ float g_cnt[GG];
__device__ float g_stats[LL * 2 * HF];       // per-layer [sum | sumsq] of raw rst
__device__ float g_norm2[(LL + 1) * 2 * HF]; // slot 0 = identity; slot l+1 = BN(l)
__device__ float g_pool[GG * LL * HF];       // RAW rst pooling accumulator
// CSR scratch
__device__ int g_cnt_i[NN];
__device__ int g_rowptr[NN];
__device__ int g_cur[NN];
__device__ int g_bsum[SCAN_B];
__device__ int g_eidx[EE];

__device__ __forceinline__ void red_add_v4(float* a, float x, float y, float z, float w) {
    asm volatile("red.global.add.v4.f32 [%0], {%1,%2,%3,%4};"
                 :: "l"(a), "f"(x), "f"(y), "f"(z), "f"(w) : "memory");
}

// ---------------- f32x2 packed-FMA helpers --------------------------------------
__device__ __forceinline__ uint64_t splat2(float x) {
    uint64_t r;
    asm("mov.b64 %0, {%1, %1};" : "=l"(r) : "f"(x));
    return r;
}
__device__ __forceinline__ void ffma2(uint64_t& d, uint64_t a, uint64_t b) {
    asm("fma.rn.f32x2 %0, %1, %2, %0;" : "+l"(d) : "l"(a), "l"(b));
}
__device__ __forceinline__ float2 unpack2(uint64_t v) {
    float2 f;
    asm("mov.b64 {%0, %1}, %2;" : "=f"(f.x), "=f"(f.y) : "l"(v));
    return f;
}
__device__ __forceinline__ uint32_t smem_u32(const void* p) {
    uint32_t a;
    asm("{ .reg .u64 t; cvta.to.shared.u64 t, %1; cvt.u32.u64 %0, t; }" : "=r"(a) : "l"(p));
    return a;
}
__device__ __forceinline__ void cp_async16(uint32_t smem, const void* gmem) {
    asm volatile("cp.async.cg.shared.global [%0], [%1], 16;" :: "r"(smem), "l"(gmem));
}
__device__ __forceinline__ void cp_commit() {
    asm volatile("cp.async.commit_group;" ::: "memory");
}
__device__ __forceinline__ void cp_wait0() {
    asm volatile("cp.async.wait_group 0;" ::: "memory");
}

// ---------------- init: h0 = emb[in_feat] -------------------------------------
__global__ void k_init(const int* __restrict__ feat, const float* __restrict__ emb) {
    int idx = blockIdx.x * blockDim.x + threadIdx.x;
    if (idx >= NN * 32) return;
    int node = idx >> 5, q = idx & 31;
    int f = __ldg(&feat[node]);
    float4 v = __ldg((const float4*)(emb + (size_t)f * HF) + q);
    *((float4*)(g_h + (size_t)node * HF) + q) = v;
}

// ---------------- CSR build ----------------------------------------------------
__global__ void k_hist(const int* __restrict__ dst) {
    int e = blockIdx.x * blockDim.x + threadIdx.x;
    if (e < EE) atomicAdd(&g_cnt_i[__ldg(&dst[e])], 1);
}

__global__ void k_scan1() {
    __shared__ int sh[SCAN_B];
    int t = threadIdx.x;
    int i = blockIdx.x * SCAN_B + t;
    int v = (i < NN) ? g_cnt_i[i] : 0;
    sh[t] = v;
    __syncthreads();
    #pragma unroll
    for (int off = 1; off < SCAN_B; off <<= 1) {
        int x = (t >= off) ? sh[t - off] : 0;
        __syncthreads();
        sh[t] += x;
        __syncthreads();
    }
    if (i < NN) g_rowptr[i] = sh[t] - v;
    if (t == SCAN_B - 1) g_bsum[blockIdx.x] = sh[t];
}

__global__ void k_scan2() {
    __shared__ int sh[256];
    int t = threadIdx.x;
    int v = (t < NB) ? g_bsum[t] : 0;
    sh[t] = v;
    __syncthreads();
    #pragma unroll
    for (int off = 1; off < 256; off <<= 1) {
        int x = (t >= off) ? sh[t - off] : 0;
        __syncthreads();
        sh[t] += x;
        __syncthreads();
    }
    if (t < NB) g_bsum[t] = sh[t] - v;
}

__global__ void k_scan3() {
    int i = blockIdx.x * blockDim.x + threadIdx.x;
    if (i >= NN) return;
    int base = g_rowptr[i] + g_bsum[i / SCAN_B];
    g_rowptr[i] = base;
    g_cur[i] = base;
    g_rdeg[i] = 1.0f / fmaxf((float)g_cnt_i[i], 1.0f);
}

__global__ void k_scatter(const int* __restrict__ src, const int* __restrict__ dst) {
    int e = blockIdx.x * blockDim.x + threadIdx.x;
    if (e >= EE) return;
    int d = __ldg(&dst[e]);
    int pos = atomicAdd(&g_cur[d], 1);
    g_eidx[pos] = __ldg(&src[e]);
}

// ---------------- graph node counts + identity norm slot -----------------------
__global__ void k_cnt(const int* __restrict__ gid) {
    __shared__ float sh[GG];
    int t = threadIdx.x;
    if (t < GG) sh[t] = 0.f;
    __syncthreads();
    int i = blockIdx.x * blockDim.x + t;
    if (i < NN) atomicAdd(&sh[__ldg(&gid[i])], 1.0f);
    __syncthreads();
    if (t < GG && sh[t] != 0.f) atomicAdd(&g_cnt[t], sh[t]);
}

__global__ void k_norm0() {
    int c = threadIdx.x;
    g_norm2[c] = 1.0f;
    g_norm2[HF + c] = 0.0f;
}

// ---------------- aggregation: CSR gather of RAW X, BN fold applied post-mean --
__global__ __launch_bounds__(256) void k_gather(const float* __restrict__ X, int slot) {
    int w = (blockIdx.x * blockDim.x + threadIdx.x) >> 5;
    if (w >= NN) return;
    int lane = threadIdx.x & 31;
    int beg = __ldg(&g_rowptr[w]);
    int cnt = __ldg(&g_cnt_i[w]);
    float4 a0 = make_float4(0.f, 0.f, 0.f, 0.f);
    float4 a1 = make_float4(0.f, 0.f, 0.f, 0.f);
    for (int base = 0; base < cnt; base += 32) {
        int idx = (base + lane < cnt) ? __ldg(&g_eidx[beg + base + lane]) : 0;
        int m = min(32, cnt - base);
        int j = 0;
        for (; j + 1 < m; j += 2) {
            int s0 = __shfl_sync(0xffffffffu, idx, j);
            int s1 = __shfl_sync(0xffffffffu, idx, j + 1);
            float4 v0 = __ldg((const float4*)(X + (size_t)s0 * HF) + lane);
            float4 v1 = __ldg((const float4*)(X + (size_t)s1 * HF) + lane);
            a0.x += v0.x; a0.y += v0.y; a0.z += v0.z; a0.w += v0.w;
            a1.x += v1.x; a1.y += v1.y; a1.z += v1.z; a1.w += v1.w;
        }
        if (j < m) {
            int s0 = __shfl_sync(0xffffffffu, idx, j);
            float4 v0 = __ldg((const float4*)(X + (size_t)s0 * HF) + lane);
            a0.x += v0.x; a0.y += v0.y; a0.z += v0.z; a0.w += v0.w;
        }
    }
    float r = __ldg(&g_rdeg[w]);
    float dz = (cnt > 0) ? 1.0f : 0.0f;   // zero-degree: mean is exactly 0 in h-space
    const float* nsc = g_norm2 + slot * 2 * HF;
    float4 sc = *((const float4*)nsc + lane);
    float4 sh = *((const float4*)(nsc + HF) + lane);
    float4 o;
    o.x = fmaf((a0.x + a1.x) * r, sc.x, sh.x * dz);
    o.y = fmaf((a0.y + a1.y) * r, sc.y, sh.y * dz);
    o.z = fmaf((a0.z + a1.z) * r, sc.z, sh.z * dz);
    o.w = fmaf((a0.w + a1.w) * r, sc.w, sh.w * dz);
    *((float4*)(g_agg + (size_t)w * HF) + lane) = o;
}

// ---------------- fused GEMM (FFMA2 16x8, double-buffered pipeline) ------------
// Unified 8-iteration loop over [BN(X) | agg] x 4 k0 tiles.
// A: register prefetch (transform needed); B: cp.async.cg 16B into back buffer.
__global__ __launch_bounds__(128) void k_gemm(
    const float* __restrict__ X, float* __restrict__ R,
    const float* __restrict__ Ws, const float* __restrict__ Wn,
    const float* __restrict__ bias, const float* __restrict__ pw,
    const int* __restrict__ gid, int l)
{
    extern __shared__ float smem[];
    float* Abuf[2] = { smem, smem + A_TILE };
    float* Bbuf[2] = { smem + 2 * A_TILE, smem + 2 * A_TILE + B_TILE };
    uint32_t bbase[2] = { smem_u32(Bbuf[0]), smem_u32(Bbuf[1]) };

    int t = threadIdx.x;
    int tx = t & 15, ty = t >> 4;
    int row0 = blockIdx.x * BM;
    const float* nsc = g_norm2 + l * 2 * HF;
    const float* nsh = nsc + HF;

    uint64_t c2[8][8];
    {
        uint64_t z = splat2(0.f);
        #pragma unroll
        for (int p = 0; p < 8; p++)
            #pragma unroll
            for (int c = 0; c < 8; c++) c2[p][c] = z;
    }

    float4 a_pf[8];

    // ---- loader lambdas (manual inline) ----
    // load A tile (iteration it) into a_pf
    #define LOAD_A(it)  {                                                        \
        int phase_ = (it) >> 2, k0_ = ((it) & 3) * BK;                           \
        const float* A_ = phase_ ? g_agg : X;                                    \
        _Pragma("unroll")                                                        \
        for (int i = 0; i < 8; i++) {                                            \
            int j = i * 128 + t;                                                 \
            int m = j >> 3, q = j & 7;                                           \
            int row = row0 + m;                                                  \
            float4 a = make_float4(0.f, 0.f, 0.f, 0.f);                          \
            if (row < NN) {                                                      \
                a = __ldg((const float4*)(A_ + (size_t)row * HF + k0_) + q);     \
                if (phase_ == 0) {                                               \
                    float4 sc = __ldg((const float4*)nsc + (k0_ >> 2) + q);      \
                    float4 sh = __ldg((const float4*)nsh + (k0_ >> 2) + q);      \
                    a.x = fmaf(a.x, sc.x, sh.x);                                 \
                    a.y = fmaf(a.y, sc.y, sh.y);                                 \
                    a.z = fmaf(a.z, sc.z, sh.z);                                 \
                    a.w = fmaf(a.w, sc.w, sh.w);                                 \
                }                                                                \
            }                                                                    \
            a_pf[i] = a;                                                         \
        }                                                                        \
    }
    // store a_pf (transposed) into Abuf[buf]
    #define STORE_A(buf) {                                                       \
        float* As_ = Abuf[buf];                                                  \
        _Pragma("unroll")                                                        \
        for (int i = 0; i < 8; i++) {                                            \
            int j = i * 128 + t;                                                 \
            int m = j >> 3, kk = (j & 7) << 2;                                   \
            As_[(kk + 0) * ASTRIDE + m] = a_pf[i].x;                             \
            As_[(kk + 1) * ASTRIDE + m] = a_pf[i].y;                             \
            As_[(kk + 2) * ASTRIDE + m] = a_pf[i].z;                             \
            As_[(kk + 3) * ASTRIDE + m] = a_pf[i].w;                             \
        }                                                                        \
    }
    // cp.async B tile (iteration it) into Bbuf[buf]
    #define LOAD_B(it, buf) {                                                    \
        int phase_ = (it) >> 2, k0_ = ((it) & 3) * BK;                           \
        const float* W_ = phase_ ? Wn : Ws;                                      \
        _Pragma("unroll")                                                        \
        for (int i = 0; i < 8; i++) {                                            \
            int j = i * 128 + t;                                                 \
            int kk = j >> 5, c4 = j & 31;                                        \
            cp_async16(bbase[buf] + (uint32_t)(kk * HF + c4 * 4) * 4u,           \
                       W_ + (size_t)(k0_ + kk) * HF + c4 * 4);                   \
        }                                                                        \
        cp_commit();                                                             \
    }

    // ---- prologue: fill buffer 0 ----
    LOAD_A(0);
    LOAD_B(0, 0);
    STORE_A(0);
    cp_wait0();
    __syncthreads();

    // ---- pipelined mainloop ----
    #pragma unroll 1
    for (int it = 0; it < 8; it++) {
        int cb = it & 1, nb = (it + 1) & 1;
        if (it < 7) {
            LOAD_A(it + 1);        // LDG in flight during compute
            LOAD_B(it + 1, nb);    // cp.async in flight during compute
        }
        const float* As = Abuf[cb];
        const float* Bs = Bbuf[cb];
        #pragma unroll
        for (int kk = 0; kk < BK; kk++) {
            ulonglong2 ap0 = *(const ulonglong2*)&As[kk * ASTRIDE + ty * 16];
            ulonglong2 ap1 = *(const ulonglong2*)&As[kk * ASTRIDE + ty * 16 + 4];
            ulonglong2 ap2 = *(const ulonglong2*)&As[kk * ASTRIDE + ty * 16 + 8];
            ulonglong2 ap3 = *(const ulonglong2*)&As[kk * ASTRIDE + ty * 16 + 12];
            uint64_t ap[8] = {ap0.x, ap0.y, ap1.x, ap1.y, ap2.x, ap2.y, ap3.x, ap3.y};
            float4 b0 = *(const float4*)&Bs[kk * HF + tx * 8];
            float4 b1 = *(const float4*)&Bs[kk * HF + tx * 8 + 4];
            float bf[8] = {b0.x, b0.y, b0.z, b0.w, b1.x, b1.y, b1.z, b1.w};
            #pragma unroll
            for (int c = 0; c < 8; c++) {
                uint64_t bs2 = splat2(bf[c]);
                #pragma unroll
                for (int p = 0; p < 8; p++)
                    ffma2(c2[p][c], ap[p], bs2);
            }
        }
        if (it < 7) {
            STORE_A(nb);
            cp_wait0();
        }
        __syncthreads();
    }

    // --- epilogue: bias, PReLU, store raw rst, stats, run-fused raw pooling ----
    float bc[8], pc[8];
    #pragma unroll
    for (int c = 0; c < 8; c++) {
        bc[c] = __ldg(&bias[tx * 8 + c]);
        pc[c] = __ldg(&pw[tx * 8 + c]);
    }
    float ps[8] = {0}, pq[8] = {0};
    float pa[8] = {0};
    int curg = -1;
    #pragma unroll
    for (int p = 0; p < 8; p++) {
        #pragma unroll
        for (int half = 0; half < 2; half++) {
            int row = row0 + ty * 16 + p * 2 + half;
            if (row < NN) {
                float v[8];
                #pragma unroll
                for (int c = 0; c < 8; c++) {
                    float2 u = unpack2(c2[p][c]);
                    float x = (half ? u.y : u.x) + bc[c];
                    x = x > 0.f ? x : pc[c] * x;
                    v[c] = x;
                    ps[c] += x;
                    pq[c] += x * x;
                }
                float4* o = (float4*)(R + (size_t)row * HF + tx * 8);
                o[0] = make_float4(v[0], v[1], v[2], v[3]);
                o[1] = make_float4(v[4], v[5], v[6], v[7]);
                int g = __ldg(&gid[row]);
                if (g != curg) {
                    if (curg >= 0) {
                        float* pp = g_pool + (size_t)curg * (LL * HF) + l * HF + tx * 8;
                        red_add_v4(pp, pa[0], pa[1], pa[2], pa[3]);
                        red_add_v4(pp + 4, pa[4], pa[5], pa[6], pa[7]);
                    }
                    curg = g;
                    #pragma unroll
                    for (int c = 0; c < 8; c++) pa[c] = v[c];
                } else {
                    #pragma unroll
                    for (int c = 0; c < 8; c++) pa[c] += v[c];
                }
            }
        }
    }
    if (curg >= 0) {
        float* pp = g_pool + (size_t)curg * (LL * HF) + l * HF + tx * 8;
        red_add_v4(pp, pa[0], pa[1], pa[2], pa[3]);
        red_add_v4(pp + 4, pa[4], pa[5], pa[6], pa[7]);
    }

    __syncthreads();   // smem free; reuse Abuf[0] for stat reduction
    float* red = Abuf[0];
    #pragma unroll
    for (int c = 0; c < 8; c++) {
        red[ty * HF + tx * 8 + c] = ps[c];
        red[1024 + ty * HF + tx * 8 + c] = pq[c];
    }
    __syncthreads();
    if (t < HF) {
        float s = 0.f, q = 0.f;
        #pragma unroll
        for (int r = 0; r < 8; r++) {
            s += red[r * HF + t];
            q += red[1024 + r * HF + t];
        }
        atomicAdd(&g_stats[l * 2 * HF + t], s);
        atomicAdd(&g_stats[l * 2 * HF + HF + t], q);
    }
    #undef LOAD_A
    #undef STORE_A
    #undef LOAD_B
}

// ---------------- BN stats finalize -> norm slot l+1 ---------------------------
__global__ void k_finalize(const float* __restrict__ gamma,
                           const float* __restrict__ beta, int l) {
    int c = threadIdx.x;
    float s = g_stats[l * 2 * HF + c];
    float q = g_stats[l * 2 * HF + HF + c];
    const float inv_n = 1.0f / (float)NN;
    float mu = s * inv_n;
    float var = fmaf(-mu, mu, q * inv_n);
    float rs = rsqrtf(var + EPS_BN);
    float sc = __ldg(&gamma[c]) * rs;
    float sh = fmaf(-mu, sc, __ldg(&beta[c]));
    g_norm2[(l + 1) * 2 * HF + c] = sc;
    g_norm2[(l + 1) * 2 * HF + HF + c] = sh;
}

// ---------------- final: mean over graph + deferred BN affine ------------------
__global__ void k_out(float* __restrict__ out) {
    int i = blockIdx.x * blockDim.x + threadIdx.x;
    if (i >= GG * LL * HF) return;
    int g = i >> 9;
    int l = (i >> 7) & 3;
    int c = i & 127;
    float cnt = g_cnt[g];
    float cz = (cnt > 0.f) ? 1.0f : 0.0f;
    float sc = g_norm2[(l + 1) * 2 * HF + c];
    float sh = g_norm2[(l + 1) * 2 * HF + HF + c];
    out[i] = fmaf(g_pool[i] / fmaxf(cnt, 1.0f), sc, sh * cz);
}

// ---------------- launch --------------------------------------------------------
extern "C" void kernel_launch(void* const* d_in, const int* in_sizes, int n_in,
                              void* d_out, int out_size) {
    const int*   in_feat = (const int*)d_in[0];
    const int*   src     = (const int*)d_in[1];
    const int*   dst     = (const int*)d_in[2];
    const int*   gid     = (const int*)d_in[3];
    const float* emb     = (const float*)d_in[4];
    const float* W_self  = (const float*)d_in[5];
    const float* W_neigh = (const float*)d_in[6];
    const float* bias    = (const float*)d_in[7];
    const float* gamma   = (const float*)d_in[8];
    const float* beta    = (const float*)d_in[9];
    const float* prelu   = (const float*)d_in[10];

    void *p_cnti, *p_cnt, *p_pool, *p_stats, *p_h, *p_rst;
    cudaGetSymbolAddress(&p_cnti, g_cnt_i);
    cudaGetSymbolAddress(&p_cnt, g_cnt);
    cudaGetSymbolAddress(&p_pool, g_pool);
    cudaGetSymbolAddress(&p_stats, g_stats);
    cudaGetSymbolAddress(&p_h, g_h);
    cudaGetSymbolAddress(&p_rst, g_rst);

    cudaFuncSetAttribute(k_gemm, cudaFuncAttributeMaxDynamicSharedMemorySize, SMEMB);

    cudaMemsetAsync(p_cnti, 0, NN * sizeof(int));
    cudaMemsetAsync(p_cnt, 0, GG * sizeof(float));
    cudaMemsetAsync(p_pool, 0, (size_t)GG * LL * HF * sizeof(float));
    cudaMemsetAsync(p_stats, 0, (size_t)LL * 2 * HF * sizeof(float));

    k_init<<<(NN * 32 + 255) / 256, 256>>>(in_feat, emb);
    k_hist<<<(EE + 255) / 256, 256>>>(dst);
    k_scan1<<<NB, SCAN_B>>>();
    k_scan2<<<1, 256>>>();
    k_scan3<<<(NN + 255) / 256, 256>>>();
    k_scatter<<<(EE + 255) / 256, 256>>>(src, dst);
    k_cnt<<<(NN + 255) / 256, 256>>>(gid);
    k_norm0<<<1, HF>>>();

    for (int l = 0; l < LL; l++) {
        const float* Xin  = (l & 1) ? (const float*)p_rst : (const float*)p_h;
        float*       Xout = (l & 1) ? (float*)p_h : (float*)p_rst;
        k_gather<<<(NN * 32 + 255) / 256, 256>>>(Xin, l);
        k_gemm<<<NTILE, 128, SMEMB>>>(Xin, Xout,
                               W_self + (size_t)l * HF * HF,
                               W_neigh + (size_t)l * HF * HF,
                               bias + l * HF, prelu + l * HF, gid, l);
        k_finalize<<<1, HF>>>(gamma + l * HF, beta + l * HF, l);
    }
    k_out<<<(GG * LL * HF + 255) / 256, 256>>>((float*)d_out);
}

// round 16
// speedup vs baseline: 1.1278x; 1.1278x over previous
#include <cuda_runtime.h>
#include <cstdint>

#define NN 100000
#define EE 1600000
#define HF 128
#define GG 128
#define LL 4
#define EPS_BN 1e-5f
#define BM 128
#define BK 32
#define ASTRIDE 132
#define SCAN_B 512
#define NB ((NN + SCAN_B - 1) / SCAN_B)   // 196
#define NTILE ((NN + BM - 1) / BM)        // 782

// ---------------- scratch (static device globals; no allocs allowed) ----------
__device__ float g_h[(size_t)NN * HF];       // buffer A (emb / raw rst ping-pong)
__device__ float g_rst[(size_t)NN * HF];     // buffer B
__device__ float g_agg[(size_t)NN * HF];     // BN-folded neighbor means
__device__ float g_rdeg[NN];
__device__ float g_cnt[GG];
__device__ float g_stats[LL * 2 * HF];       // per-layer [sum | sumsq] of raw rst
__device__ float g_norm2[(LL + 1) * 2 * HF]; // slot 0 = identity; slot l+1 = BN(l)
__device__ float g_pool[GG * LL * HF];       // RAW rst pooling accumulator
__device__ int   g_done[LL];                 // per-layer gemm block completion counter
// CSR scratch
__device__ int g_cnt_i[NN];
__device__ int g_rowptr[NN];
__device__ int g_cur[NN];
__device__ int g_bsum[SCAN_B];
__device__ int g_eidx[EE];

__device__ __forceinline__ void red_add_v4(float* a, float x, float y, float z, float w) {
    asm volatile("red.global.add.v4.f32 [%0], {%1,%2,%3,%4};"
                 :: "l"(a), "f"(x), "f"(y), "f"(z), "f"(w) : "memory");
}

// ---------------- f32x2 packed-FMA helpers --------------------------------------
__device__ __forceinline__ uint64_t splat2(float x) {
    uint64_t r;
    asm("mov.b64 %0, {%1, %1};" : "=l"(r) : "f"(x));
    return r;
}
__device__ __forceinline__ void ffma2(uint64_t& d, uint64_t a, uint64_t b) {
    asm("fma.rn.f32x2 %0, %1, %2, %0;" : "+l"(d) : "l"(a), "l"(b));
}
__device__ __forceinline__ float2 unpack2(uint64_t v) {
    float2 f;
    asm("mov.b64 {%0, %1}, %2;" : "=f"(f.x), "=f"(f.y) : "l"(v));
    return f;
}
__device__ __forceinline__ uint32_t smem_u32(const void* p) {
    uint32_t a;
    asm("{ .reg .u64 t; cvta.to.shared.u64 t, %1; cvt.u32.u64 %0, t; }" : "=r"(a) : "l"(p));
    return a;
}
__device__ __forceinline__ void cp_async16(uint32_t smem, const void* gmem) {
    asm volatile("cp.async.cg.shared.global [%0], [%1], 16;" :: "r"(smem), "l"(gmem));
}
__device__ __forceinline__ void cp_commit() {
    asm volatile("cp.async.commit_group;" ::: "memory");
}
__device__ __forceinline__ void cp_wait0() {
    asm volatile("cp.async.wait_group 0;" ::: "memory");
}

// ---------------- init: h0 = emb[in_feat] -------------------------------------
__global__ void k_init(const int* __restrict__ feat, const float* __restrict__ emb) {
    int idx = blockIdx.x * blockDim.x + threadIdx.x;
    if (idx >= NN * 32) return;
    int node = idx >> 5, q = idx & 31;
    int f = __ldg(&feat[node]);
    float4 v = __ldg((const float4*)(emb + (size_t)f * HF) + q);
    *((float4*)(g_h + (size_t)node * HF) + q) = v;
}

// ---------------- CSR build ----------------------------------------------------
__global__ void k_hist(const int* __restrict__ dst) {
    int e = blockIdx.x * blockDim.x + threadIdx.x;
    if (e < EE) atomicAdd(&g_cnt_i[__ldg(&dst[e])], 1);
}

__global__ void k_scan1() {
    __shared__ int sh[SCAN_B];
    int t = threadIdx.x;
    int i = blockIdx.x * SCAN_B + t;
    int v = (i < NN) ? g_cnt_i[i] : 0;
    sh[t] = v;
    __syncthreads();
    #pragma unroll
    for (int off = 1; off < SCAN_B; off <<= 1) {
        int x = (t >= off) ? sh[t - off] : 0;
        __syncthreads();
        sh[t] += x;
        __syncthreads();
    }
    if (i < NN) g_rowptr[i] = sh[t] - v;
    if (t == SCAN_B - 1) g_bsum[blockIdx.x] = sh[t];
}

__global__ void k_scan2() {
    __shared__ int sh[256];
    int t = threadIdx.x;
    int v = (t < NB) ? g_bsum[t] : 0;
    sh[t] = v;
    __syncthreads();
    #pragma unroll
    for (int off = 1; off < 256; off <<= 1) {
        int x = (t >= off) ? sh[t - off] : 0;
        __syncthreads();
        sh[t] += x;
        __syncthreads();
    }
    if (t < NB) g_bsum[t] = sh[t] - v;
}

__global__ void k_scan3() {
    int i = blockIdx.x * blockDim.x + threadIdx.x;
    if (i < HF && blockIdx.x == 0) {   // fold norm slot-0 init (identity) here
        g_norm2[i] = 1.0f;
        g_norm2[HF + i] = 0.0f;
    }
    if (i >= NN) return;
    int base = g_rowptr[i] + g_bsum[i / SCAN_B];
    g_rowptr[i] = base;
    g_cur[i] = base;
    g_rdeg[i] = 1.0f / fmaxf((float)g_cnt_i[i], 1.0f);
}

__global__ void k_scatter(const int* __restrict__ src, const int* __restrict__ dst) {
    int e = blockIdx.x * blockDim.x + threadIdx.x;
    if (e >= EE) return;
    int d = __ldg(&dst[e]);
    int pos = atomicAdd(&g_cur[d], 1);
    g_eidx[pos] = __ldg(&src[e]);
}

// ---------------- graph node counts --------------------------------------------
__global__ void k_cnt(const int* __restrict__ gid) {
    __shared__ float sh[GG];
    int t = threadIdx.x;
    if (t < GG) sh[t] = 0.f;
    __syncthreads();
    int i = blockIdx.x * blockDim.x + t;
    if (i < NN) atomicAdd(&sh[__ldg(&gid[i])], 1.0f);
    __syncthreads();
    if (t < GG && sh[t] != 0.f) atomicAdd(&g_cnt[t], sh[t]);
}

// ---------------- aggregation: CSR gather of RAW X, BN fold applied post-mean --
__global__ __launch_bounds__(256) void k_gather(const float* __restrict__ X, int slot) {
    int w = (blockIdx.x * blockDim.x + threadIdx.x) >> 5;
    if (w >= NN) return;
    int lane = threadIdx.x & 31;
    int beg = __ldg(&g_rowptr[w]);
    int cnt = __ldg(&g_cnt_i[w]);
    float4 a0 = make_float4(0.f, 0.f, 0.f, 0.f);
    float4 a1 = make_float4(0.f, 0.f, 0.f, 0.f);
    for (int base = 0; base < cnt; base += 32) {
        int idx = (base + lane < cnt) ? __ldg(&g_eidx[beg + base + lane]) : 0;
        int m = min(32, cnt - base);
        int j = 0;
        for (; j + 1 < m; j += 2) {
            int s0 = __shfl_sync(0xffffffffu, idx, j);
            int s1 = __shfl_sync(0xffffffffu, idx, j + 1);
            float4 v0 = __ldg((const float4*)(X + (size_t)s0 * HF) + lane);
            float4 v1 = __ldg((const float4*)(X + (size_t)s1 * HF) + lane);
            a0.x += v0.x; a0.y += v0.y; a0.z += v0.z; a0.w += v0.w;
            a1.x += v1.x; a1.y += v1.y; a1.z += v1.z; a1.w += v1.w;
        }
        if (j < m) {
            int s0 = __shfl_sync(0xffffffffu, idx, j);
            float4 v0 = __ldg((const float4*)(X + (size_t)s0 * HF) + lane);
            a0.x += v0.x; a0.y += v0.y; a0.z += v0.z; a0.w += v0.w;
        }
    }
    float r = __ldg(&g_rdeg[w]);
    float dz = (cnt > 0) ? 1.0f : 0.0f;   // zero-degree: mean is exactly 0 in h-space
    const float* nsc = g_norm2 + slot * 2 * HF;
    float4 sc = *((const float4*)nsc + lane);
    float4 sh = *((const float4*)(nsc + HF) + lane);
    float4 o;
    o.x = fmaf((a0.x + a1.x) * r, sc.x, sh.x * dz);
    o.y = fmaf((a0.y + a1.y) * r, sc.y, sh.y * dz);
    o.z = fmaf((a0.z + a1.z) * r, sc.z, sh.z * dz);
    o.w = fmaf((a0.w + a1.w) * r, sc.w, sh.w * dz);
    *((float4*)(g_agg + (size_t)w * HF) + lane) = o;
}

// ---------------- fused GEMM (FFMA2 16x8, cp.async B, folded BN finalize) ------
// 128 threads; thread = 16 rows x 8 cols; accumulators packed along M.
// Last block to finish computes BN scale/shift for slot l+1 (no separate launch).
__global__ __launch_bounds__(128) void k_gemm(
    const float* __restrict__ X, float* __restrict__ R,
    const float* __restrict__ Ws, const float* __restrict__ Wn,
    const float* __restrict__ bias, const float* __restrict__ pw,
    const float* __restrict__ gamma, const float* __restrict__ beta,
    const int* __restrict__ gid, int l)
{
    __shared__ float As[BK * ASTRIDE];
    __shared__ float Bs[BK * HF];
    __shared__ int s_last;

    int t = threadIdx.x;
    int tx = t & 15, ty = t >> 4;
    int row0 = blockIdx.x * BM;
    const float* nsc = g_norm2 + l * 2 * HF;
    const float* nsh = nsc + HF;
    uint32_t bs_base = smem_u32(Bs);

    uint64_t c2[8][8];
    {
        uint64_t z = splat2(0.f);
        #pragma unroll
        for (int p = 0; p < 8; p++)
            #pragma unroll
            for (int c = 0; c < 8; c++) c2[p][c] = z;
    }

    #pragma unroll
    for (int phase = 0; phase < 2; phase++) {
        const float* A = phase ? g_agg : X;
        const float* W = phase ? Wn : Ws;
        for (int k0 = 0; k0 < HF; k0 += BK) {
            // B tile via cp.async first — copies proceed while A loader runs
            #pragma unroll
            for (int i = 0; i < 8; i++) {
                int j = i * 128 + t;
                int kk = j >> 5, c4 = j & 31;
                cp_async16(bs_base + (uint32_t)(kk * HF + c4 * 4) * 4u,
                           W + (size_t)(k0 + kk) * HF + c4 * 4);
            }
            cp_commit();
            // A tile loader: 128 rows x 32 k (transposed into As[k][m])
            #pragma unroll
            for (int i = 0; i < 8; i++) {
                int j = i * 128 + t;
                int m = j >> 3;
                int kk = (j & 7) << 2;
                int row = row0 + m;
                float4 a = make_float4(0.f, 0.f, 0.f, 0.f);
                if (row < NN) {
                    a = __ldg((const float4*)(A + (size_t)row * HF + k0) + (j & 7));
                    if (phase == 0) {   // fold BN of previous layer into self path
                        float4 sc = __ldg((const float4*)nsc + (k0 >> 2) + (j & 7));
                        float4 sh = __ldg((const float4*)nsh + (k0 >> 2) + (j & 7));
                        a.x = fmaf(a.x, sc.x, sh.x);
                        a.y = fmaf(a.y, sc.y, sh.y);
                        a.z = fmaf(a.z, sc.z, sh.z);
                        a.w = fmaf(a.w, sc.w, sh.w);
                    }
                }
                As[(kk + 0) * ASTRIDE + m] = a.x;
                As[(kk + 1) * ASTRIDE + m] = a.y;
                As[(kk + 2) * ASTRIDE + m] = a.z;
                As[(kk + 3) * ASTRIDE + m] = a.w;
            }
            cp_wait0();
            __syncthreads();
            #pragma unroll
            for (int kk = 0; kk < BK; kk++) {
                ulonglong2 ap0 = *(const ulonglong2*)&As[kk * ASTRIDE + ty * 16];
                ulonglong2 ap1 = *(const ulonglong2*)&As[kk * ASTRIDE + ty * 16 + 4];
                ulonglong2 ap2 = *(const ulonglong2*)&As[kk * ASTRIDE + ty * 16 + 8];
                ulonglong2 ap3 = *(const ulonglong2*)&As[kk * ASTRIDE + ty * 16 + 12];
                uint64_t ap[8] = {ap0.x, ap0.y, ap1.x, ap1.y, ap2.x, ap2.y, ap3.x, ap3.y};
                float4 b0 = *(const float4*)&Bs[kk * HF + tx * 8];
                float4 b1 = *(const float4*)&Bs[kk * HF + tx * 8 + 4];
                float bf[8] = {b0.x, b0.y, b0.z, b0.w, b1.x, b1.y, b1.z, b1.w};
                #pragma unroll
                for (int c = 0; c < 8; c++) {
                    uint64_t bs2 = splat2(bf[c]);
                    #pragma unroll
                    for (int p = 0; p < 8; p++)
                        ffma2(c2[p][c], ap[p], bs2);
                }
            }
            __syncthreads();
        }
    }

    // --- epilogue: bias, PReLU, store raw rst, stats, run-fused raw pooling ----
    float bc[8], pc[8];
    #pragma unroll
    for (int c = 0; c < 8; c++) {
        bc[c] = __ldg(&bias[tx * 8 + c]);
        pc[c] = __ldg(&pw[tx * 8 + c]);
    }
    float ps[8] = {0}, pq[8] = {0};
    float pa[8] = {0};
    int curg = -1;
    #pragma unroll
    for (int p = 0; p < 8; p++) {
        #pragma unroll
        for (int half = 0; half < 2; half++) {
            int row = row0 + ty * 16 + p * 2 + half;
            if (row < NN) {
                float v[8];
                #pragma unroll
                for (int c = 0; c < 8; c++) {
                    float2 u = unpack2(c2[p][c]);
                    float x = (half ? u.y : u.x) + bc[c];
                    x = x > 0.f ? x : pc[c] * x;
                    v[c] = x;
                    ps[c] += x;
                    pq[c] += x * x;
                }
                float4* o = (float4*)(R + (size_t)row * HF + tx * 8);
                o[0] = make_float4(v[0], v[1], v[2], v[3]);
                o[1] = make_float4(v[4], v[5], v[6], v[7]);
                int g = __ldg(&gid[row]);
                if (g != curg) {
                    if (curg >= 0) {
                        float* pp = g_pool + (size_t)curg * (LL * HF) + l * HF + tx * 8;
                        red_add_v4(pp, pa[0], pa[1], pa[2], pa[3]);
                        red_add_v4(pp + 4, pa[4], pa[5], pa[6], pa[7]);
                    }
                    curg = g;
                    #pragma unroll
                    for (int c = 0; c < 8; c++) pa[c] = v[c];
                } else {
                    #pragma unroll
                    for (int c = 0; c < 8; c++) pa[c] += v[c];
                }
            }
        }
    }
    if (curg >= 0) {
        float* pp = g_pool + (size_t)curg * (LL * HF) + l * HF + tx * 8;
        red_add_v4(pp, pa[0], pa[1], pa[2], pa[3]);
        red_add_v4(pp + 4, pa[4], pa[5], pa[6], pa[7]);
    }

    __syncthreads();   // done with Bs as W tile; reuse for stat reduction
    #pragma unroll
    for (int c = 0; c < 8; c++) {
        Bs[ty * HF + tx * 8 + c] = ps[c];
        Bs[1024 + ty * HF + tx * 8 + c] = pq[c];
    }
    __syncthreads();
    if (t < HF) {
        float s = 0.f, q = 0.f;
        #pragma unroll
        for (int r = 0; r < 8; r++) {
            s += Bs[r * HF + t];
            q += Bs[1024 + r * HF + t];
        }
        atomicAdd(&g_stats[l * 2 * HF + t], s);
        atomicAdd(&g_stats[l * 2 * HF + HF + t], q);
    }

    // --- last block finalizes BN scale/shift for slot l+1 ----------------------
    __threadfence();
    __syncthreads();
    if (t == 0)
        s_last = (atomicAdd(&g_done[l], 1) == (int)gridDim.x - 1) ? 1 : 0;
    __syncthreads();
    if (s_last && t < HF) {
        __threadfence();
        float s = __ldcg(&g_stats[l * 2 * HF + t]);
        float q = __ldcg(&g_stats[l * 2 * HF + HF + t]);
        const float inv_n = 1.0f / (float)NN;
        float mu = s * inv_n;
        float var = fmaf(-mu, mu, q * inv_n);
        float rs = rsqrtf(var + EPS_BN);
        float sc = __ldg(&gamma[t]) * rs;
        float sh = fmaf(-mu, sc, __ldg(&beta[t]));
        g_norm2[(l + 1) * 2 * HF + t] = sc;
        g_norm2[(l + 1) * 2 * HF + HF + t] = sh;
    }
}

// ---------------- final: mean over graph + deferred BN affine ------------------
__global__ void k_out(float* __restrict__ out) {
    int i = blockIdx.x * blockDim.x + threadIdx.x;
    if (i >= GG * LL * HF) return;
    int g = i >> 9;
    int l = (i >> 7) & 3;
    int c = i & 127;
    float cnt = g_cnt[g];
    float cz = (cnt > 0.f) ? 1.0f : 0.0f;
    float sc = g_norm2[(l + 1) * 2 * HF + c];
    float sh = g_norm2[(l + 1) * 2 * HF + HF + c];
    out[i] = fmaf(g_pool[i] / fmaxf(cnt, 1.0f), sc, sh * cz);
}

// ---------------- launch --------------------------------------------------------
extern "C" void kernel_launch(void* const* d_in, const int* in_sizes, int n_in,
                              void* d_out, int out_size) {
    const int*   in_feat = (const int*)d_in[0];
    const int*   src     = (const int*)d_in[1];
    const int*   dst     = (const int*)d_in[2];
    const int*   gid     = (const int*)d_in[3];
    const float* emb     = (const float*)d_in[4];
    const float* W_self  = (const float*)d_in[5];
    const float* W_neigh = (const float*)d_in[6];
    const float* bias    = (const float*)d_in[7];
    const float* gamma   = (const float*)d_in[8];
    const float* beta    = (const float*)d_in[9];
    const float* prelu   = (const float*)d_in[10];

    void *p_cnti, *p_cnt, *p_pool, *p_stats, *p_h, *p_rst, *p_done;
    cudaGetSymbolAddress(&p_cnti, g_cnt_i);
    cudaGetSymbolAddress(&p_cnt, g_cnt);
    cudaGetSymbolAddress(&p_pool, g_pool);
    cudaGetSymbolAddress(&p_stats, g_stats);
    cudaGetSymbolAddress(&p_h, g_h);
    cudaGetSymbolAddress(&p_rst, g_rst);
    cudaGetSymbolAddress(&p_done, g_done);

    cudaMemsetAsync(p_cnti, 0, NN * sizeof(int));
    cudaMemsetAsync(p_cnt, 0, GG * sizeof(float));
    cudaMemsetAsync(p_pool, 0, (size_t)GG * LL * HF * sizeof(float));
    cudaMemsetAsync(p_stats, 0, (size_t)LL * 2 * HF * sizeof(float));
    cudaMemsetAsync(p_done, 0, LL * sizeof(int));

    k_init<<<(NN * 32 + 255) / 256, 256>>>(in_feat, emb);
    k_hist<<<(EE + 255) / 256, 256>>>(dst);
    k_scan1<<<NB, SCAN_B>>>();
    k_scan2<<<1, 256>>>();
    k_scan3<<<(NN + 255) / 256, 256>>>();
    k_scatter<<<(EE + 255) / 256, 256>>>(src, dst);
    k_cnt<<<(NN + 255) / 256, 256>>>(gid);

    for (int l = 0; l < LL; l++) {
        const float* Xin  = (l & 1) ? (const float*)p_rst : (const float*)p_h;
        float*       Xout = (l & 1) ? (float*)p_h : (float*)p_rst;
        k_gather<<<(NN * 32 + 255) / 256, 256>>>(Xin, l);
        k_gemm<<<NTILE, 128>>>(Xin, Xout,
                               W_self + (size_t)l * HF * HF,
                               W_neigh + (size_t)l * HF * HF,
                               bias + l * HF, prelu + l * HF,
                               gamma + l * HF, beta + l * HF, gid, l);
    }
    k_out<<<(GG * LL * HF + 255) / 256, 256>>>((float*)d_out);
}